// round 15
// baseline (speedup 1.0000x reference)
#include <cuda_runtime.h>
#include <cuda_bf16.h>
#include <mma.h>
#include <math.h>
#include <stdint.h>

#define BB 2
#define NN 8192
#define CIN 64
#define CC 128
#define KK 16
#define EPSV 1e-5f

__device__ int   g_idx[BB*NN*KK];
__device__ float g_nf [(size_t)BB*NN*CC];
__device__ float g_aq [(size_t)BB*NN*CC];
__device__ float g_ak [(size_t)BB*NN*CC];
__device__ float g_v  [(size_t)BB*NN*CC];
__device__ float g_y5 [(size_t)BB*NN*CC];
__device__ float g_t1 [(size_t)BB*NN*KK*CC];
__device__ float g_M  [CC*CC];
__device__ float g_Wq2[CC*CC];
__device__ float g_Wk2[CC*CC];
__device__ float g_ccv[CC];
__device__ float g_mom[BB*64*12];
__device__ float g_part2[(size_t)BB*2048*16];
__device__ float g_part3[BB*128*16];
__device__ float g_sc1[BB*CC], g_sh1[BB*CC];
__device__ float g_sc2[BB*CC], g_sh2[BB*CC];
__device__ float g_sc3[BB*CC], g_sh3[BB*CC];

// smem byte offsets for the wmma att kernels (64-row tiles, 2 CTAs/SM)
#define PA 136              // bf16 pitch for A/B tiles
#define PD 132              // f32 pitch for D tile
#define OFF_CO  0           // 2048 B (128 float4) or 1024 B (float2)
#define OFF_JSH 2048        // 64 int
#define OFF_REL 2304        // 64 float4
#define OFF_SAC 3328        // 16 float
#define OFF_AH  4096        // 64*PA*2 = 17408
#define OFF_AL  21504       // 17408
#define OFF_BH  38912       // 128*PA*2 = 34816
#define OFF_BL  73728       // 34816
#define OFF_D   4096        // 64*PD*4 = 33792, ALIASES AH+AL (A dead after mma)
#define SMT2    108544

extern __shared__ float dsm[];

__device__ __forceinline__ void split2(float a, float b, unsigned &h, unsigned &l) {
  __nv_bfloat16 ha = __float2bfloat16_rn(a), hb = __float2bfloat16_rn(b);
  h = ((unsigned)__bfloat16_as_ushort(hb) << 16) | __bfloat16_as_ushort(ha);
  __nv_bfloat16 la = __float2bfloat16_rn(a - __bfloat162float(ha));
  __nv_bfloat16 lb = __float2bfloat16_rn(b - __bfloat162float(hb));
  l = ((unsigned)__bfloat16_as_ushort(lb) << 16) | __bfloat16_as_ushort(la);
}

#define SPLIT8(v, hi, lo) { \
  split2(v[0],v[1],hi.x,lo.x); split2(v[2],v[3],hi.y,lo.y); \
  split2(v[4],v[5],hi.z,lo.z); split2(v[6],v[7],hi.w,lo.w); }

// ---- wmma GEMM: D[64x128] = A[64x128] @ B^T; D aliases A (sync inside) -----
__device__ __forceinline__ void wmma_gemm64(char* smc, int warp) {
  using namespace nvcuda;
  const __nv_bfloat16* Ah = (const __nv_bfloat16*)(smc + OFF_AH);
  const __nv_bfloat16* Al = (const __nv_bfloat16*)(smc + OFF_AL);
  const __nv_bfloat16* Bh = (const __nv_bfloat16*)(smc + OFF_BH);
  const __nv_bfloat16* Bl = (const __nv_bfloat16*)(smc + OFF_BL);
  float* D = (float*)(smc + OFF_D);
  int rb = warp >> 1, ch = warp & 1;          // rows rb*16, cols ch*64
  wmma::fragment<wmma::accumulator,16,16,16,float> acc[4];
  #pragma unroll
  for (int n = 0; n < 4; n++) wmma::fill_fragment(acc[n], 0.f);
  #pragma unroll
  for (int k = 0; k < 8; k++) {
    wmma::fragment<wmma::matrix_a,16,16,16,__nv_bfloat16,wmma::row_major> ah, al;
    wmma::load_matrix_sync(ah, Ah + (rb*16)*PA + k*16, PA);
    wmma::load_matrix_sync(al, Al + (rb*16)*PA + k*16, PA);
    #pragma unroll
    for (int n = 0; n < 4; n++) {
      wmma::fragment<wmma::matrix_b,16,16,16,__nv_bfloat16,wmma::col_major> bh, bl;
      wmma::load_matrix_sync(bh, Bh + (ch*64 + n*16)*PA + k*16, PA);
      wmma::load_matrix_sync(bl, Bl + (ch*64 + n*16)*PA + k*16, PA);
      wmma::mma_sync(acc[n], ah, bh, acc[n]);
      wmma::mma_sync(acc[n], ah, bl, acc[n]);
      wmma::mma_sync(acc[n], al, bh, acc[n]);
    }
  }
  __syncthreads();   // all warps done READING A before D overwrites it
  #pragma unroll
  for (int n = 0; n < 4; n++)
    wmma::store_matrix_sync(D + (rb*16)*PD + ch*64 + n*16, acc[n], PD, wmma::mem_row_major);
}

__device__ __forceinline__ void build_wtile(const float* __restrict__ W, char* smc, int tid) {
  int row = tid >> 1, half = tid & 1;
  const float* src = W + row*CC + half*64;
  __nv_bfloat16* bh = (__nv_bfloat16*)(smc + OFF_BH) + row*PA + half*64;
  __nv_bfloat16* bl = (__nv_bfloat16*)(smc + OFF_BL) + row*PA + half*64;
  #pragma unroll
  for (int cc = 0; cc < 8; cc++) {
    float v[8];
    float4 f0 = *(const float4*)(src + cc*8);
    float4 f1 = *(const float4*)(src + cc*8 + 4);
    v[0]=f0.x;v[1]=f0.y;v[2]=f0.z;v[3]=f0.w;v[4]=f1.x;v[5]=f1.y;v[6]=f1.z;v[7]=f1.w;
    uint4 hi, lo; SPLIT8(v, hi, lo);
    *(uint4*)(bh + cc*8) = hi;
    *(uint4*)(bl + cc*8) = lo;
  }
}

#define GSTEP16(wv, base) { \
  float4 x0=*(const float4*)((base));    float4 x1=*(const float4*)((base)+4); \
  float4 x2=*(const float4*)((base)+8);  float4 x3=*(const float4*)((base)+12); \
  acc[0]=fmaf(wv,x0.x,acc[0]);  acc[1]=fmaf(wv,x0.y,acc[1]); \
  acc[2]=fmaf(wv,x0.z,acc[2]);  acc[3]=fmaf(wv,x0.w,acc[3]); \
  acc[4]=fmaf(wv,x1.x,acc[4]);  acc[5]=fmaf(wv,x1.y,acc[5]); \
  acc[6]=fmaf(wv,x1.z,acc[6]);  acc[7]=fmaf(wv,x1.w,acc[7]); \
  acc[8]=fmaf(wv,x2.x,acc[8]);  acc[9]=fmaf(wv,x2.y,acc[9]); \
  acc[10]=fmaf(wv,x2.z,acc[10]);acc[11]=fmaf(wv,x2.w,acc[11]); \
  acc[12]=fmaf(wv,x3.x,acc[12]);acc[13]=fmaf(wv,x3.y,acc[13]); \
  acc[14]=fmaf(wv,x3.z,acc[14]);acc[15]=fmaf(wv,x3.w,acc[15]); }

// ------- kNN (thread per query) + rel-moment partials for GN1 ---------------
__global__ void __launch_bounds__(128) k_knn(const float* __restrict__ xyz) {
  __shared__ float4 sp[1024];
  __shared__ float red[4*9];
  int b = blockIdx.y;
  int n = blockIdx.x * 128 + threadIdx.x;
  int tid = threadIdx.x, lane = tid & 31, wid = tid >> 5;
  const float* xb = xyz + (size_t)b * 3 * NN;
  float qx = xb[n], qy = xb[NN + n], qz = xb[2 * NN + n];
  float qsq = __fadd_rn(__fadd_rn(__fmul_rn(qx,qx), __fmul_rn(qy,qy)), __fmul_rn(qz,qz));
  float bd[16]; int bi[16];
  #pragma unroll
  for (int i = 0; i < 16; i++) { bd[i] = 3.4e38f; bi[i] = 0; }
  float worstv = 3.4e38f; int worsts = 0;
  for (int t0 = 0; t0 < NN; t0 += 1024) {
    __syncthreads();
    for (int e = tid; e < 1024; e += 128) {
      float x = xb[t0+e], y = xb[NN+t0+e], z = xb[2*NN+t0+e];
      float sq = __fadd_rn(__fadd_rn(__fmul_rn(x,x), __fmul_rn(y,y)), __fmul_rn(z,z));
      sp[e] = make_float4(x, y, z, sq);
    }
    __syncthreads();
    for (int j = 0; j < 1024; j++) {
      float4 c = sp[j];
      float inner = __fadd_rn(__fadd_rn(__fmul_rn(qx,c.x), __fmul_rn(qy,c.y)), __fmul_rn(qz,c.z));
      float d2 = __fsub_rn(__fadd_rn(qsq, c.w), __fmul_rn(2.0f, inner));
      if (d2 < worstv) {
        int ci = t0 + j;
        #pragma unroll
        for (int i = 0; i < 16; i++) if (i == worsts) { bd[i] = d2; bi[i] = ci; }
        worstv = bd[0]; worsts = 0;
        #pragma unroll
        for (int i = 1; i < 16; i++) if (bd[i] > worstv) { worstv = bd[i]; worsts = i; }
      }
    }
  }
  int* outp = g_idx + ((size_t)b * NN + n) * KK;
  float m[9];
  #pragma unroll
  for (int q = 0; q < 9; q++) m[q] = 0.f;
  #pragma unroll
  for (int i = 0; i < 16; i++) {
    int j = bi[i];
    outp[i] = j;
    float rx = xb[j]-qx, ry = xb[NN+j]-qy, rz = xb[2*NN+j]-qz;
    m[0]+=rx; m[1]+=ry; m[2]+=rz;
    m[3]=fmaf(rx,rx,m[3]); m[4]=fmaf(ry,ry,m[4]); m[5]=fmaf(rz,rz,m[5]);
    m[6]=fmaf(rx,ry,m[6]); m[7]=fmaf(rx,rz,m[7]); m[8]=fmaf(ry,rz,m[8]);
  }
  #pragma unroll
  for (int q = 0; q < 9; q++) {
    float v = m[q];
    #pragma unroll
    for (int off = 16; off >= 1; off >>= 1) v += __shfl_down_sync(0xffffffffu, v, off);
    if (lane == 0) red[wid*9+q] = v;
  }
  __syncthreads();
  if (tid < 9) {
    float a = red[tid] + red[9+tid] + red[18+tid] + red[27+tid];
    g_mom[((size_t)b*64 + blockIdx.x)*12 + tid] = a;
  }
}

// ------- k_prep: z=0 pre-conv; z=1 weight folding + GN1 finalize ------------
__global__ void __launch_bounds__(256) k_prep(
    const float* __restrict__ feat, const float* __restrict__ preW, const float* __restrict__ preB,
    const float* __restrict__ A1, const float* __restrict__ Wq, const float* __restrict__ Wk,
    const float* __restrict__ W2, const float* __restrict__ a1b, const float* __restrict__ qb,
    const float* __restrict__ kb, const float* __restrict__ p2b,
    const float* __restrict__ p1w, const float* __restrict__ p1b,
    const float* __restrict__ g1, const float* __restrict__ be1) {
  int tid = threadIdx.x;
  if (blockIdx.z == 0) {
    __shared__ float wr[CC*65];
    __shared__ float buf[2*CIN*20];
    int grp = tid >> 7, co = tid & 127;
    for (int e = tid; e < CC*CIN; e += 256) wr[(e>>6)*65 + (e&63)] = preW[e];
    int b = blockIdx.y;
    int n0 = blockIdx.x*32 + grp*16;
    const float* fb = feat + (size_t)b * CIN * NN;
    for (int e = tid; e < 2*CIN*16; e += 256) {
      int g2 = e >> 10, ci = (e >> 4) & 63, p = e & 15;
      buf[g2*(CIN*20) + ci*20 + p] = fb[(size_t)ci*NN + blockIdx.x*32 + g2*16 + p];
    }
    __syncthreads();
    float* gb = buf + grp*(CIN*20);
    float acc[16]; float bv = preB[co];
    #pragma unroll
    for (int p = 0; p < 16; p++) acc[p] = bv;
    #pragma unroll 4
    for (int ci = 0; ci < CIN; ci++) { float w = wr[co*65+ci]; GSTEP16(w, gb + ci*20); }
    float* yb = g_nf + ((size_t)b*NN + n0) * CC;
    #pragma unroll
    for (int p = 0; p < 16; p++) yb[(size_t)p*CC + co] = acc[p];
    return;
  }
  int x = blockIdx.x;
  if (x < 3) {
    if (blockIdx.y != 0) return;
    const float* X = (x==0) ? Wq : ((x==1) ? Wk : W2);
    float* O = (x==0) ? g_Wq2 : ((x==1) ? g_Wk2 : g_M);
    for (int e = tid; e < CC*CC; e += 256) {
      int o = e >> 7, c = e & 127;
      float s0=0.f, s1=0.f;
      for (int j = 0; j < CC; j += 2) {
        s0 = fmaf(A1[o*CC+j],   X[j*CC+c],     s0);
        s1 = fmaf(A1[o*CC+j+1], X[(j+1)*CC+c], s1);
      }
      O[e] = s0 + s1;
    }
  } else if (x == 3) {
    if (blockIdx.y != 0) return;
    for (int c = tid; c < CC; c += 256) {
      float s = a1b[c];
      for (int j = 0; j < CC; j++) s = fmaf(A1[c*CC+j], qb[j]-kb[j]+p2b[j], s);
      g_ccv[c] = s;
    }
  } else if (x == 4) {
    int b = blockIdx.y;
    __shared__ double S[9];
    __shared__ double chS[128], chSS[128];
    __shared__ double gsum[8], gss[8];
    if (tid < 9) {
      double a = 0.0;
      for (int k = 0; k < 64; k++) a += (double)g_mom[((size_t)b*64+k)*12 + tid];
      S[tid] = a;
    }
    __syncthreads();
    if (tid < 128) {
      int c = tid;
      double w0 = p1w[c*3], w1 = p1w[c*3+1], w2 = p1w[c*3+2], bb = p1b[c];
      double wS = w0*S[0] + w1*S[1] + w2*S[2];
      double cnt1 = 131072.0;
      chS[c]  = wS + bb*cnt1;
      chSS[c] = w0*w0*S[3] + w1*w1*S[4] + w2*w2*S[5]
              + 2.0*(w0*w1*S[6] + w0*w2*S[7] + w1*w2*S[8])
              + 2.0*bb*wS + bb*bb*cnt1;
    }
    __syncthreads();
    if (tid < 8) {
      double s = 0.0, ss = 0.0;
      for (int i = 0; i < 16; i++) { s += chS[tid*16+i]; ss += chSS[tid*16+i]; }
      gsum[tid] = s; gss[tid] = ss;
    }
    __syncthreads();
    if (tid < 128) {
      int g = tid >> 4;
      double cnt = 2097152.0;
      double mean = gsum[g] / cnt;
      double var  = gss[g] / cnt - mean*mean;
      float rstd = rsqrtf((float)var + EPSV);
      float scv = g1[tid] * rstd;
      g_sc1[b*CC+tid] = scv;
      g_sh1[b*CC+tid] = be1[tid] - (float)mean * scv;
    }
  }
}

// ---------------- stats reduce ----------------------------------------------
__global__ void k_reduce(int which, int nblkb, float invcnt,
                         const float* __restrict__ gamma, const float* __restrict__ beta) {
  const float* P = (which==1) ? g_part2 : g_part3;
  float* sc = (which==1) ? g_sc2 : g_sc3;
  float* sh = (which==1) ? g_sh2 : g_sh3;
  int b = blockIdx.x, tid = threadIdx.x;
  int s = tid & 15, grp = tid >> 4;
  double acc = 0.0;
  for (int blk = grp; blk < nblkb; blk += 16)
    acc += (double)P[((size_t)b*nblkb + blk)*16 + s];
  __shared__ double rr[16][17];
  __shared__ double fin[16];
  rr[grp][s] = acc;
  __syncthreads();
  if (tid < 16) { double t = 0.0; for (int i = 0; i < 16; i++) t += rr[i][tid]; fin[tid] = t; }
  __syncthreads();
  if (tid < CC) {
    int g8 = tid >> 4;
    double mean = fin[g8] * (double)invcnt;
    double var  = fin[8+g8] * (double)invcnt - mean*mean;
    float rstd = rsqrtf((float)var + EPSV);
    float scv = gamma[tid] * rstd;
    sc[b*CC+tid] = scv;
    sh[b*CC+tid] = beta[tid] - (float)mean * scv;
  }
}

// ------ QKV conv ------------------------------------------------------------
__global__ void __launch_bounds__(256) k_convQKV(const float* __restrict__ Wv,
                                                 const float* __restrict__ a1b,
                                                 const float* __restrict__ vb) {
  float* wr = dsm;
  float* gb = dsm + CC*129;
  int tid = threadIdx.x, grp = tid >> 7, co = tid & 127;
  int b = blockIdx.y, z = blockIdx.z;
  const float* W = (z==0) ? g_Wq2 : ((z==1) ? g_Wk2 : Wv);
  const float* bias = (z==2) ? vb : a1b;
  float* Y = (z==0) ? g_aq : ((z==1) ? g_ak : g_v);
  for (int e = tid; e < CC*CC; e += 256) wr[(e>>7)*129 + (e&127)] = W[e];
  float bv = bias[co];
  float* g = gb + grp*(CC*20);
  for (int it = 0; it < 2; it++) {
    size_t r0 = (size_t)b*NN + (size_t)(blockIdx.x*2 + it)*32 + grp*16;
    __syncthreads();
    #pragma unroll
    for (int p = 0; p < 16; p++) g[co*20+p] = g_nf[(r0+p)*CC + co];
    __syncthreads();
    float acc[16];
    #pragma unroll
    for (int p = 0; p < 16; p++) acc[p] = bv;
    #pragma unroll 4
    for (int ci = 0; ci < CC; ci++) { float w = wr[co*129+ci]; GSTEP16(w, g + ci*20); }
    #pragma unroll
    for (int p = 0; p < 16; p++) Y[(r0+p)*CC + co] = acc[p];
  }
}

// ---------------- att1 wmma kernel (64-row tiles, 2 CTAs/SM) ----------------
__global__ void __launch_bounds__(256, 2) k_att1_w(const float* __restrict__ xyz,
                                                   const float* __restrict__ p1w,
                                                   const float* __restrict__ p1b) {
  char* smc = (char*)dsm;
  int tid = threadIdx.x, b = blockIdx.y;
  int warp = tid >> 5, lane = tid & 31;
  if (tid < 128) {
    float s1 = g_sc1[b*CC+tid], h1 = g_sh1[b*CC+tid];
    ((float4*)(smc+OFF_CO))[tid] = make_float4(s1*p1w[tid*3], s1*p1w[tid*3+1],
                                               s1*p1w[tid*3+2], fmaf(s1, p1b[tid], h1));
  }
  build_wtile(g_M, smc, tid);
  const float* xb = xyz + (size_t)b*3*NN;
  int row = tid >> 2, q4 = tid & 3;               // build mapping: 64 rows x 4 quarters
  int sub = warp & 1, cq = warp >> 1;             // epilogue: rows sub*32+lane, cols cq*32
  int er = sub*32 + lane, colb = cq*32;
  __nv_bfloat16* Ahp = (__nv_bfloat16*)(smc+OFF_AH) + row*PA + q4*32;
  __nv_bfloat16* Alp = (__nv_bfloat16*)(smc+OFF_AL) + row*PA + q4*32;
  const float* Drow = (const float*)(smc+OFF_D) + (size_t)er*PD + colb;
  for (int tl = blockIdx.x; tl < 2048; tl += gridDim.x) {
    int n0 = tl*4;
    size_t r0 = ((size_t)b*NN + n0)*16;
    __syncthreads();
    if (tid < 64) {
      int j = g_idx[r0 + tid];
      ((int*)(smc+OFF_JSH))[tid] = j;
      int nq = n0 + (tid >> 4);
      float4 rr;
      rr.x = xb[j]-xb[nq]; rr.y = xb[NN+j]-xb[NN+nq]; rr.z = xb[2*NN+j]-xb[2*NN+nq]; rr.w = 0.f;
      ((float4*)(smc+OFF_REL))[tid] = rr;
    }
    if (tid < 16) ((float*)(smc+OFF_SAC))[tid] = 0.f;
    __syncthreads();
    float4 rl = ((float4*)(smc+OFF_REL))[row];
    const float4* co4 = (const float4*)(smc+OFF_CO) + q4*32;
    #pragma unroll
    for (int g = 0; g < 4; g++) {
      float v[8];
      #pragma unroll
      for (int i = 0; i < 8; i++) {
        float4 c4 = co4[g*8+i];
        float y = fmaf(c4.x, rl.x, fmaf(c4.y, rl.y, fmaf(c4.z, rl.z, c4.w)));
        v[i] = (y >= 0.f) ? y : 0.1f*y;
      }
      uint4 hi, lo; SPLIT8(v, hi, lo);
      *(uint4*)(Ahp + g*8) = hi;
      *(uint4*)(Alp + g*8) = lo;
    }
    __syncthreads();
    wmma_gemm64(smc, warp);
    __syncthreads();
    int nq = n0 + (er >> 4), j = ((int*)(smc+OFF_JSH))[er];
    const float4* aqp = (const float4*)(g_aq + ((size_t)b*NN + nq)*CC + colb);
    const float4* akp = (const float4*)(g_ak + ((size_t)b*NN + j)*CC + colb);
    const float4* cvp = (const float4*)(g_ccv + colb);
    float4* op = (float4*)(g_t1 + (r0 + er)*CC + colb);
    float ts0=0.f, ts1=0.f, tss0=0.f, tss1=0.f;
    #pragma unroll
    for (int q = 0; q < 8; q++) {
      const float4 d = *(const float4*)(Drow + q*4);
      float4 aq = aqp[q], ak = akp[q], cv = cvp[q], vv;
      vv.x = d.x + cv.x + aq.x - ak.x;
      vv.y = d.y + cv.y + aq.y - ak.y;
      vv.z = d.z + cv.z + aq.z - ak.z;
      vv.w = d.w + cv.w + aq.w - ak.w;
      op[q] = vv;
      float s = vv.x + vv.y + vv.z + vv.w;
      float ss = fmaf(vv.x,vv.x,fmaf(vv.y,vv.y,fmaf(vv.z,vv.z,vv.w*vv.w)));
      if (q < 4) { ts0 += s; tss0 += ss; } else { ts1 += s; tss1 += ss; }
    }
    #pragma unroll
    for (int off = 16; off >= 1; off >>= 1) {
      ts0  += __shfl_down_sync(0xffffffffu, ts0, off);
      ts1  += __shfl_down_sync(0xffffffffu, ts1, off);
      tss0 += __shfl_down_sync(0xffffffffu, tss0, off);
      tss1 += __shfl_down_sync(0xffffffffu, tss1, off);
    }
    if (lane == 0) {
      float* sa = (float*)(smc+OFF_SAC);
      atomicAdd(&sa[2*cq],     ts0); atomicAdd(&sa[2*cq+1],     ts1);
      atomicAdd(&sa[8+2*cq],  tss0); atomicAdd(&sa[8+2*cq+1],  tss1);
    }
    __syncthreads();
    if (tid < 16) g_part2[((size_t)b*2048 + tl)*16 + tid] = ((float*)(smc+OFF_SAC))[tid];
  }
}

// ---------------- att2 wmma kernel (softmax + V-agg + residual) -------------
__global__ void __launch_bounds__(256, 2) k_att2_w(const float* __restrict__ W) {
  char* smc = (char*)dsm;
  int tid = threadIdx.x, b = blockIdx.y;
  int warp = tid >> 5, lane = tid & 31;
  if (tid < 128)
    ((float2*)(smc+OFF_CO))[tid] = make_float2(g_sc2[b*CC+tid], g_sh2[b*CC+tid]);
  build_wtile(W, smc, tid);
  int row = tid >> 2, q4 = tid & 3;
  int sub = warp & 1, cq = warp >> 1;
  int er = sub*32 + lane, colb = cq*32, kk = er & 15;
  __nv_bfloat16* Ahp = (__nv_bfloat16*)(smc+OFF_AH) + row*PA + q4*32;
  __nv_bfloat16* Alp = (__nv_bfloat16*)(smc+OFF_AL) + row*PA + q4*32;
  const float* Drow = (const float*)(smc+OFF_D) + (size_t)er*PD + colb;
  for (int tl = blockIdx.x; tl < 2048; tl += gridDim.x) {
    int n0 = tl*4;
    size_t r0 = ((size_t)b*NN + n0)*16;
    __syncthreads();
    if (tid < 64) ((int*)(smc+OFF_JSH))[tid] = g_idx[r0 + tid];
    __syncthreads();
    {
      const float4* tp = (const float4*)(g_t1 + (r0 + row)*CC + q4*32);
      const float2* c2 = (const float2*)(smc+OFF_CO) + q4*32;
      #pragma unroll
      for (int g = 0; g < 4; g++) {
        float4 f0 = tp[g*2], f1 = tp[g*2+1];
        float v[8] = {f0.x,f0.y,f0.z,f0.w,f1.x,f1.y,f1.z,f1.w};
        #pragma unroll
        for (int i = 0; i < 8; i++) {
          float2 c = c2[g*8+i];
          float y = fmaf(c.x, v[i], c.y);
          v[i] = (y >= 0.f) ? y : 0.1f*y;
        }
        uint4 hi, lo; SPLIT8(v, hi, lo);
        *(uint4*)(Ahp + g*8) = hi;
        *(uint4*)(Alp + g*8) = lo;
      }
    }
    __syncthreads();
    wmma_gemm64(smc, warp);
    __syncthreads();
    int nq = n0 + (er >> 4), j = ((int*)(smc+OFF_JSH))[er];
    const float4* vp = (const float4*)(g_v + ((size_t)b*NN + j)*CC + colb);
    const float4* np = (const float4*)(g_nf + ((size_t)b*NN + nq)*CC + colb);
    float4* yp = (float4*)(g_y5 + ((size_t)b*NN + nq)*CC + colb);
    #pragma unroll
    for (int q = 0; q < 8; q++) {
      float4 x = *(const float4*)(Drow + q*4);
      float4 m = x;
      #pragma unroll
      for (int off = 8; off >= 1; off >>= 1) {
        m.x = fmaxf(m.x, __shfl_xor_sync(0xffffffffu, m.x, off, 16));
        m.y = fmaxf(m.y, __shfl_xor_sync(0xffffffffu, m.y, off, 16));
        m.z = fmaxf(m.z, __shfl_xor_sync(0xffffffffu, m.z, off, 16));
        m.w = fmaxf(m.w, __shfl_xor_sync(0xffffffffu, m.w, off, 16));
      }
      float4 e;
      e.x = __expf(x.x - m.x); e.y = __expf(x.y - m.y);
      e.z = __expf(x.z - m.z); e.w = __expf(x.w - m.w);
      float4 s = e;
      #pragma unroll
      for (int off = 8; off >= 1; off >>= 1) {
        s.x += __shfl_xor_sync(0xffffffffu, s.x, off, 16);
        s.y += __shfl_xor_sync(0xffffffffu, s.y, off, 16);
        s.z += __shfl_xor_sync(0xffffffffu, s.z, off, 16);
        s.w += __shfl_xor_sync(0xffffffffu, s.w, off, 16);
      }
      float4 vv = vp[q], oo;
      oo.x = e.x/s.x*vv.x; oo.y = e.y/s.y*vv.y;
      oo.z = e.z/s.z*vv.z; oo.w = e.w/s.w*vv.w;
      #pragma unroll
      for (int off = 8; off >= 1; off >>= 1) {
        oo.x += __shfl_xor_sync(0xffffffffu, oo.x, off, 16);
        oo.y += __shfl_xor_sync(0xffffffffu, oo.y, off, 16);
        oo.z += __shfl_xor_sync(0xffffffffu, oo.z, off, 16);
        oo.w += __shfl_xor_sync(0xffffffffu, oo.w, off, 16);
      }
      if (kk == 0) {
        float4 nf = np[q], r;
        r.x = oo.x + nf.x; r.y = oo.y + nf.y; r.z = oo.z + nf.z; r.w = oo.w + nf.w;
        yp[q] = r;
      }
    }
  }
}

// ---------------- post conv + stats -----------------------------------------
__global__ void __launch_bounds__(256) k_conv_post(const float* __restrict__ X,
                                                   const float* __restrict__ W,
                                                   const float* __restrict__ bias,
                                                   float* __restrict__ Y) {
  float* wr = dsm;
  float* gb = dsm + CC*129;
  float* sacc = gb + 2*CC*20;
  int tid = threadIdx.x, grp = tid >> 7, co = tid & 127, lane = tid & 31;
  int b = blockIdx.y;
  for (int e = tid; e < CC*CC; e += 256) wr[(e>>7)*129 + (e&127)] = W[e];
  if (tid < 16) sacc[tid] = 0.f;
  float bv = bias[co];
  float* g = gb + grp*(CC*20);
  float ts = 0.f, tss = 0.f;
  for (int it = 0; it < 2; it++) {
    size_t r0 = (size_t)b*NN + (size_t)(blockIdx.x*2 + it)*32 + grp*16;
    __syncthreads();
    #pragma unroll
    for (int p = 0; p < 16; p++) g[co*20+p] = X[(r0+p)*CC + co];
    __syncthreads();
    float acc[16];
    #pragma unroll
    for (int p = 0; p < 16; p++) acc[p] = bv;
    #pragma unroll 4
    for (int ci = 0; ci < CC; ci++) { float w = wr[co*129+ci]; GSTEP16(w, g + ci*20); }
    #pragma unroll
    for (int p = 0; p < 16; p++) { Y[(r0+p)*CC + co] = acc[p]; ts += acc[p]; tss = fmaf(acc[p],acc[p],tss); }
  }
  #pragma unroll
  for (int off = 8; off >= 1; off >>= 1) {
    ts  += __shfl_down_sync(0xffffffffu, ts, off, 16);
    tss += __shfl_down_sync(0xffffffffu, tss, off, 16);
  }
  if ((lane & 15) == 0) {
    int cgg = co >> 4;
    atomicAdd(&sacc[cgg], ts); atomicAdd(&sacc[8+cgg], tss);
  }
  __syncthreads();
  if (tid < 16) g_part3[((size_t)b*gridDim.x + blockIdx.x)*16 + tid] = sacc[tid];
}

// ---------------- final GN3 + lrelu + transpose -----------------------------
__global__ void k_final(float* __restrict__ out) {
  __shared__ float t[32][33];
  int b = blockIdx.z, c0 = blockIdx.y*32, n0 = blockIdx.x*32;
  int tx = threadIdx.x, ty = threadIdx.y;
  float scv = g_sc3[b*CC + c0 + tx], shv = g_sh3[b*CC + c0 + tx];
  #pragma unroll
  for (int i = 0; i < 4; i++) {
    int n = n0 + ty*4 + i;
    float x = g_aq[((size_t)b*NN + n)*CC + c0 + tx];
    float y = fmaf(scv, x, shv);
    t[tx][ty*4+i] = (y >= 0.f) ? y : 0.1f*y;
  }
  __syncthreads();
  #pragma unroll
  for (int i = 0; i < 4; i++) {
    int c = c0 + ty*4 + i;
    out[((size_t)b*CC + c)*NN + n0 + tx] = t[ty*4+i][tx];
  }
}

// ---------------- launch ----------------------------------------------------
extern "C" void kernel_launch(void* const* d_in, const int* in_sizes, int n_in,
                              void* d_out, int out_size) {
  const float* xyz    = (const float*)d_in[0];
  const float* feat   = (const float*)d_in[1];
  const float* pre_w  = (const float*)d_in[2];
  const float* pre_b  = (const float*)d_in[3];
  const float* wq_w   = (const float*)d_in[4];
  const float* wq_b   = (const float*)d_in[5];
  const float* wk_w   = (const float*)d_in[6];
  const float* wk_b   = (const float*)d_in[7];
  const float* wv_w   = (const float*)d_in[8];
  const float* wv_b   = (const float*)d_in[9];
  const float* pos1_w = (const float*)d_in[10];
  const float* pos1_b = (const float*)d_in[11];
  const float* pos1_g = (const float*)d_in[12];
  const float* pos1_be= (const float*)d_in[13];
  const float* att1_b = (const float*)d_in[17];
  const float* att1_g = (const float*)d_in[18];
  const float* att1_be= (const float*)d_in[19];
  const float* att2_w = (const float*)d_in[20];
  const float* post_w = (const float*)d_in[22];
  const float* post_b = (const float*)d_in[23];
  const float* post_g = (const float*)d_in[24];
  const float* post_be= (const float*)d_in[25];
  float* out = (float*)d_out;

  const int SMEMC = (CC*129 + 2*CC*20 + 16) * 4;
  cudaFuncSetAttribute(k_convQKV,  cudaFuncAttributeMaxDynamicSharedMemorySize, SMEMC);
  cudaFuncSetAttribute(k_conv_post,cudaFuncAttributeMaxDynamicSharedMemorySize, SMEMC);
  cudaFuncSetAttribute(k_att1_w,   cudaFuncAttributeMaxDynamicSharedMemorySize, SMT2);
  cudaFuncSetAttribute(k_att2_w,   cudaFuncAttributeMaxDynamicSharedMemorySize, SMT2);

  void *p_y5, *p_aq;
  cudaGetSymbolAddress(&p_y5, g_y5);
  cudaGetSymbolAddress(&p_aq, g_aq);

  k_knn<<<dim3(NN/128, BB), 128>>>(xyz);                               // 1
  k_prep<<<dim3(256, BB, 2), 256>>>(feat, pre_w, pre_b,                // 2
      (const float*)d_in[16], wq_w, wk_w, (const float*)d_in[14],
      att1_b, wq_b, wk_b, (const float*)d_in[15],
      pos1_w, pos1_b, pos1_g, pos1_be);
  k_convQKV<<<dim3(128, BB, 3), 256, SMEMC>>>(wv_w, att1_b, wv_b);     // 3
  k_att1_w<<<dim3(148, BB), 256, SMT2>>>(xyz, pos1_w, pos1_b);         // 4 = PROFILED
  k_reduce<<<2, 256>>>(1, 2048, 1.f/2097152.f, att1_g, att1_be);       // 5
  k_att2_w<<<dim3(148, BB), 256, SMT2>>>(att2_w);                      // 6
  k_conv_post<<<dim3(128, BB), 256, SMEMC>>>((const float*)p_y5, post_w, post_b, (float*)p_aq); // 7
  k_reduce<<<2, 256>>>(2, 128, 1.f/131072.f, post_g, post_be);         // 8
  k_final<<<dim3(NN/32, CC/32, BB), dim3(32, 8)>>>(out);               // 9
}

// round 16
// speedup vs baseline: 1.6410x; 1.6410x over previous
#include <cuda_runtime.h>
#include <cuda_bf16.h>
#include <mma.h>
#include <math.h>
#include <stdint.h>

#define BB 2
#define NN 8192
#define CIN 64
#define CC 128
#define KK 16
#define EPSV 1e-5f

__device__ int   g_idx[BB*NN*KK];
__device__ float g_nf [(size_t)BB*NN*CC];
__device__ float g_aq [(size_t)BB*NN*CC];
__device__ float g_ak [(size_t)BB*NN*CC];
__device__ float g_v  [(size_t)BB*NN*CC];
__device__ float g_y5 [(size_t)BB*NN*CC];
__device__ float g_t1 [(size_t)BB*NN*KK*CC];
__device__ float g_M  [CC*CC];
__device__ float g_Wq2[CC*CC];
__device__ float g_Wk2[CC*CC];
__device__ float g_ccv[CC];
__device__ float g_mom[BB*64*12];
__device__ float g_part2[(size_t)BB*512*16];
__device__ float g_part3[BB*128*16];
__device__ float g_sc1[BB*CC], g_sh1[BB*CC];
__device__ float g_sc2[BB*CC], g_sh2[BB*CC];
__device__ float g_sc3[BB*CC], g_sh3[BB*CC];

// smem byte offsets for the wmma att kernels (256-row tiles, 1 CTA/SM)
#define PA 136              // bf16 pitch for A/B tiles
#define PD 132              // f32 pitch for D tile
#define OFF_CO  0           // 2048 B
#define OFF_JSH 2048        // 256 int = 1024
#define OFF_REL 3072        // 256 float4 = 4096
#define OFF_SAC 7168        // 16 float
#define OFF_AH  8192        // 256*PA*2 = 69632
#define OFF_AL  77824       // 69632
#define OFF_BH  147456      // 128*PA*2 = 34816
#define OFF_BL  182272      // 34816
#define OFF_D   8192        // 256*PD*4 = 135168, aliases AH+AL (A dead after mma)
#define SMT3    217088

extern __shared__ float dsm[];

__device__ __forceinline__ void split2(float a, float b, unsigned &h, unsigned &l) {
  __nv_bfloat16 ha = __float2bfloat16_rn(a), hb = __float2bfloat16_rn(b);
  h = ((unsigned)__bfloat16_as_ushort(hb) << 16) | __bfloat16_as_ushort(ha);
  __nv_bfloat16 la = __float2bfloat16_rn(a - __bfloat162float(ha));
  __nv_bfloat16 lb = __float2bfloat16_rn(b - __bfloat162float(hb));
  l = ((unsigned)__bfloat16_as_ushort(lb) << 16) | __bfloat16_as_ushort(la);
}

#define SPLIT8(v, hi, lo) { \
  split2(v[0],v[1],hi.x,lo.x); split2(v[2],v[3],hi.y,lo.y); \
  split2(v[4],v[5],hi.z,lo.z); split2(v[6],v[7],hi.w,lo.w); }

// ---- wmma GEMM: D[256x128] = A[256x128] @ B^T; D aliases A (sync inside) ---
__device__ __forceinline__ void wmma_gemm256(char* smc, int warp) {
  using namespace nvcuda;
  const __nv_bfloat16* Ah = (const __nv_bfloat16*)(smc + OFF_AH);
  const __nv_bfloat16* Al = (const __nv_bfloat16*)(smc + OFF_AL);
  const __nv_bfloat16* Bh = (const __nv_bfloat16*)(smc + OFF_BH);
  const __nv_bfloat16* Bl = (const __nv_bfloat16*)(smc + OFF_BL);
  float* D = (float*)(smc + OFF_D);
  int rb = warp >> 1, ch = warp & 1;        // rows rb*64, cols ch*64
  wmma::fragment<wmma::accumulator,16,16,16,float> acc[4][4];
  #pragma unroll
  for (int r = 0; r < 4; r++)
    #pragma unroll
    for (int n = 0; n < 4; n++) wmma::fill_fragment(acc[r][n], 0.f);
  #pragma unroll
  for (int k = 0; k < 8; k++) {
    wmma::fragment<wmma::matrix_b,16,16,16,__nv_bfloat16,wmma::col_major> bh[4], bl[4];
    #pragma unroll
    for (int n = 0; n < 4; n++) {
      wmma::load_matrix_sync(bh[n], Bh + (ch*64 + n*16)*PA + k*16, PA);
      wmma::load_matrix_sync(bl[n], Bl + (ch*64 + n*16)*PA + k*16, PA);
    }
    #pragma unroll
    for (int r = 0; r < 4; r++) {
      wmma::fragment<wmma::matrix_a,16,16,16,__nv_bfloat16,wmma::row_major> ah, al;
      wmma::load_matrix_sync(ah, Ah + (rb*64 + r*16)*PA + k*16, PA);
      wmma::load_matrix_sync(al, Al + (rb*64 + r*16)*PA + k*16, PA);
      #pragma unroll
      for (int n = 0; n < 4; n++) {
        wmma::mma_sync(acc[r][n], ah, bh[n], acc[r][n]);
        wmma::mma_sync(acc[r][n], ah, bl[n], acc[r][n]);
        wmma::mma_sync(acc[r][n], al, bh[n], acc[r][n]);
      }
    }
  }
  __syncthreads();   // all warps done reading A before D overwrites it
  #pragma unroll
  for (int r = 0; r < 4; r++)
    #pragma unroll
    for (int n = 0; n < 4; n++)
      wmma::store_matrix_sync(D + (rb*64 + r*16)*PD + ch*64 + n*16, acc[r][n], PD, wmma::mem_row_major);
}

__device__ __forceinline__ void build_wtile(const float* __restrict__ W, char* smc, int tid) {
  int row = tid >> 1, half = tid & 1;
  const float* src = W + row*CC + half*64;
  __nv_bfloat16* bh = (__nv_bfloat16*)(smc + OFF_BH) + row*PA + half*64;
  __nv_bfloat16* bl = (__nv_bfloat16*)(smc + OFF_BL) + row*PA + half*64;
  #pragma unroll
  for (int cc = 0; cc < 8; cc++) {
    float v[8];
    float4 f0 = *(const float4*)(src + cc*8);
    float4 f1 = *(const float4*)(src + cc*8 + 4);
    v[0]=f0.x;v[1]=f0.y;v[2]=f0.z;v[3]=f0.w;v[4]=f1.x;v[5]=f1.y;v[6]=f1.z;v[7]=f1.w;
    uint4 hi, lo; SPLIT8(v, hi, lo);
    *(uint4*)(bh + cc*8) = hi;
    *(uint4*)(bl + cc*8) = lo;
  }
}

#define GSTEP16(wv, base) { \
  float4 x0=*(const float4*)((base));    float4 x1=*(const float4*)((base)+4); \
  float4 x2=*(const float4*)((base)+8);  float4 x3=*(const float4*)((base)+12); \
  acc[0]=fmaf(wv,x0.x,acc[0]);  acc[1]=fmaf(wv,x0.y,acc[1]); \
  acc[2]=fmaf(wv,x0.z,acc[2]);  acc[3]=fmaf(wv,x0.w,acc[3]); \
  acc[4]=fmaf(wv,x1.x,acc[4]);  acc[5]=fmaf(wv,x1.y,acc[5]); \
  acc[6]=fmaf(wv,x1.z,acc[6]);  acc[7]=fmaf(wv,x1.w,acc[7]); \
  acc[8]=fmaf(wv,x2.x,acc[8]);  acc[9]=fmaf(wv,x2.y,acc[9]); \
  acc[10]=fmaf(wv,x2.z,acc[10]);acc[11]=fmaf(wv,x2.w,acc[11]); \
  acc[12]=fmaf(wv,x3.x,acc[12]);acc[13]=fmaf(wv,x3.y,acc[13]); \
  acc[14]=fmaf(wv,x3.z,acc[14]);acc[15]=fmaf(wv,x3.w,acc[15]); }

// ------- kNN (thread per query) + rel-moment partials for GN1 ---------------
__global__ void __launch_bounds__(128) k_knn(const float* __restrict__ xyz) {
  __shared__ float4 sp[1024];
  __shared__ float red[4*9];
  int b = blockIdx.y;
  int n = blockIdx.x * 128 + threadIdx.x;
  int tid = threadIdx.x, lane = tid & 31, wid = tid >> 5;
  const float* xb = xyz + (size_t)b * 3 * NN;
  float qx = xb[n], qy = xb[NN + n], qz = xb[2 * NN + n];
  float qsq = __fadd_rn(__fadd_rn(__fmul_rn(qx,qx), __fmul_rn(qy,qy)), __fmul_rn(qz,qz));
  float bd[16]; int bi[16];
  #pragma unroll
  for (int i = 0; i < 16; i++) { bd[i] = 3.4e38f; bi[i] = 0; }
  float worstv = 3.4e38f; int worsts = 0;
  for (int t0 = 0; t0 < NN; t0 += 1024) {
    __syncthreads();
    for (int e = tid; e < 1024; e += 128) {
      float x = xb[t0+e], y = xb[NN+t0+e], z = xb[2*NN+t0+e];
      float sq = __fadd_rn(__fadd_rn(__fmul_rn(x,x), __fmul_rn(y,y)), __fmul_rn(z,z));
      sp[e] = make_float4(x, y, z, sq);
    }
    __syncthreads();
    for (int j = 0; j < 1024; j++) {
      float4 c = sp[j];
      float inner = __fadd_rn(__fadd_rn(__fmul_rn(qx,c.x), __fmul_rn(qy,c.y)), __fmul_rn(qz,c.z));
      float d2 = __fsub_rn(__fadd_rn(qsq, c.w), __fmul_rn(2.0f, inner));
      if (d2 < worstv) {
        int ci = t0 + j;
        #pragma unroll
        for (int i = 0; i < 16; i++) if (i == worsts) { bd[i] = d2; bi[i] = ci; }
        worstv = bd[0]; worsts = 0;
        #pragma unroll
        for (int i = 1; i < 16; i++) if (bd[i] > worstv) { worstv = bd[i]; worsts = i; }
      }
    }
  }
  int* outp = g_idx + ((size_t)b * NN + n) * KK;
  float m[9];
  #pragma unroll
  for (int q = 0; q < 9; q++) m[q] = 0.f;
  #pragma unroll
  for (int i = 0; i < 16; i++) {
    int j = bi[i];
    outp[i] = j;
    float rx = xb[j]-qx, ry = xb[NN+j]-qy, rz = xb[2*NN+j]-qz;
    m[0]+=rx; m[1]+=ry; m[2]+=rz;
    m[3]=fmaf(rx,rx,m[3]); m[4]=fmaf(ry,ry,m[4]); m[5]=fmaf(rz,rz,m[5]);
    m[6]=fmaf(rx,ry,m[6]); m[7]=fmaf(rx,rz,m[7]); m[8]=fmaf(ry,rz,m[8]);
  }
  #pragma unroll
  for (int q = 0; q < 9; q++) {
    float v = m[q];
    #pragma unroll
    for (int off = 16; off >= 1; off >>= 1) v += __shfl_down_sync(0xffffffffu, v, off);
    if (lane == 0) red[wid*9+q] = v;
  }
  __syncthreads();
  if (tid < 9) {
    float a = red[tid] + red[9+tid] + red[18+tid] + red[27+tid];
    g_mom[((size_t)b*64 + blockIdx.x)*12 + tid] = a;
  }
}

// ------- k_prep: z=0 pre-conv; z=1 weight folding + GN1 finalize ------------
__global__ void __launch_bounds__(256) k_prep(
    const float* __restrict__ feat, const float* __restrict__ preW, const float* __restrict__ preB,
    const float* __restrict__ A1, const float* __restrict__ Wq, const float* __restrict__ Wk,
    const float* __restrict__ W2, const float* __restrict__ a1b, const float* __restrict__ qb,
    const float* __restrict__ kb, const float* __restrict__ p2b,
    const float* __restrict__ p1w, const float* __restrict__ p1b,
    const float* __restrict__ g1, const float* __restrict__ be1) {
  int tid = threadIdx.x;
  if (blockIdx.z == 0) {
    __shared__ float wr[CC*65];
    __shared__ float buf[2*CIN*20];
    int grp = tid >> 7, co = tid & 127;
    for (int e = tid; e < CC*CIN; e += 256) wr[(e>>6)*65 + (e&63)] = preW[e];
    int b = blockIdx.y;
    int n0 = blockIdx.x*32 + grp*16;
    const float* fb = feat + (size_t)b * CIN * NN;
    for (int e = tid; e < 2*CIN*16; e += 256) {
      int g2 = e >> 10, ci = (e >> 4) & 63, p = e & 15;
      buf[g2*(CIN*20) + ci*20 + p] = fb[(size_t)ci*NN + blockIdx.x*32 + g2*16 + p];
    }
    __syncthreads();
    float* gb = buf + grp*(CIN*20);
    float acc[16]; float bv = preB[co];
    #pragma unroll
    for (int p = 0; p < 16; p++) acc[p] = bv;
    #pragma unroll 4
    for (int ci = 0; ci < CIN; ci++) { float w = wr[co*65+ci]; GSTEP16(w, gb + ci*20); }
    float* yb = g_nf + ((size_t)b*NN + n0) * CC;
    #pragma unroll
    for (int p = 0; p < 16; p++) yb[(size_t)p*CC + co] = acc[p];
    return;
  }
  int x = blockIdx.x;
  if (x < 3) {
    if (blockIdx.y != 0) return;
    const float* X = (x==0) ? Wq : ((x==1) ? Wk : W2);
    float* O = (x==0) ? g_Wq2 : ((x==1) ? g_Wk2 : g_M);
    for (int e = tid; e < CC*CC; e += 256) {
      int o = e >> 7, c = e & 127;
      float s0=0.f, s1=0.f;
      for (int j = 0; j < CC; j += 2) {
        s0 = fmaf(A1[o*CC+j],   X[j*CC+c],     s0);
        s1 = fmaf(A1[o*CC+j+1], X[(j+1)*CC+c], s1);
      }
      O[e] = s0 + s1;
    }
  } else if (x == 3) {
    if (blockIdx.y != 0) return;
    for (int c = tid; c < CC; c += 256) {
      float s = a1b[c];
      for (int j = 0; j < CC; j++) s = fmaf(A1[c*CC+j], qb[j]-kb[j]+p2b[j], s);
      g_ccv[c] = s;
    }
  } else if (x == 4) {
    int b = blockIdx.y;
    __shared__ double S[9];
    __shared__ double chS[128], chSS[128];
    __shared__ double gsum[8], gss[8];
    if (tid < 9) {
      double a = 0.0;
      for (int k = 0; k < 64; k++) a += (double)g_mom[((size_t)b*64+k)*12 + tid];
      S[tid] = a;
    }
    __syncthreads();
    if (tid < 128) {
      int c = tid;
      double w0 = p1w[c*3], w1 = p1w[c*3+1], w2 = p1w[c*3+2], bb = p1b[c];
      double wS = w0*S[0] + w1*S[1] + w2*S[2];
      double cnt1 = 131072.0;
      chS[c]  = wS + bb*cnt1;
      chSS[c] = w0*w0*S[3] + w1*w1*S[4] + w2*w2*S[5]
              + 2.0*(w0*w1*S[6] + w0*w2*S[7] + w1*w2*S[8])
              + 2.0*bb*wS + bb*bb*cnt1;
    }
    __syncthreads();
    if (tid < 8) {
      double s = 0.0, ss = 0.0;
      for (int i = 0; i < 16; i++) { s += chS[tid*16+i]; ss += chSS[tid*16+i]; }
      gsum[tid] = s; gss[tid] = ss;
    }
    __syncthreads();
    if (tid < 128) {
      int g = tid >> 4;
      double cnt = 2097152.0;
      double mean = gsum[g] / cnt;
      double var  = gss[g] / cnt - mean*mean;
      float rstd = rsqrtf((float)var + EPSV);
      float scv = g1[tid] * rstd;
      g_sc1[b*CC+tid] = scv;
      g_sh1[b*CC+tid] = be1[tid] - (float)mean * scv;
    }
  }
}

// ---------------- stats reduce ----------------------------------------------
__global__ void k_reduce(int which, int nblkb, float invcnt,
                         const float* __restrict__ gamma, const float* __restrict__ beta) {
  const float* P = (which==1) ? g_part2 : g_part3;
  float* sc = (which==1) ? g_sc2 : g_sc3;
  float* sh = (which==1) ? g_sh2 : g_sh3;
  int b = blockIdx.x, tid = threadIdx.x;
  int s = tid & 15, grp = tid >> 4;
  double acc = 0.0;
  for (int blk = grp; blk < nblkb; blk += 16)
    acc += (double)P[((size_t)b*nblkb + blk)*16 + s];
  __shared__ double rr[16][17];
  __shared__ double fin[16];
  rr[grp][s] = acc;
  __syncthreads();
  if (tid < 16) { double t = 0.0; for (int i = 0; i < 16; i++) t += rr[i][tid]; fin[tid] = t; }
  __syncthreads();
  if (tid < CC) {
    int g8 = tid >> 4;
    double mean = fin[g8] * (double)invcnt;
    double var  = fin[8+g8] * (double)invcnt - mean*mean;
    float rstd = rsqrtf((float)var + EPSV);
    float scv = gamma[tid] * rstd;
    sc[b*CC+tid] = scv;
    sh[b*CC+tid] = beta[tid] - (float)mean * scv;
  }
}

// ------ QKV conv ------------------------------------------------------------
__global__ void __launch_bounds__(256) k_convQKV(const float* __restrict__ Wv,
                                                 const float* __restrict__ a1b,
                                                 const float* __restrict__ vb) {
  float* wr = dsm;
  float* gb = dsm + CC*129;
  int tid = threadIdx.x, grp = tid >> 7, co = tid & 127;
  int b = blockIdx.y, z = blockIdx.z;
  const float* W = (z==0) ? g_Wq2 : ((z==1) ? g_Wk2 : Wv);
  const float* bias = (z==2) ? vb : a1b;
  float* Y = (z==0) ? g_aq : ((z==1) ? g_ak : g_v);
  for (int e = tid; e < CC*CC; e += 256) wr[(e>>7)*129 + (e&127)] = W[e];
  float bv = bias[co];
  float* g = gb + grp*(CC*20);
  for (int it = 0; it < 2; it++) {
    size_t r0 = (size_t)b*NN + (size_t)(blockIdx.x*2 + it)*32 + grp*16;
    __syncthreads();
    #pragma unroll
    for (int p = 0; p < 16; p++) g[co*20+p] = g_nf[(r0+p)*CC + co];
    __syncthreads();
    float acc[16];
    #pragma unroll
    for (int p = 0; p < 16; p++) acc[p] = bv;
    #pragma unroll 4
    for (int ci = 0; ci < CC; ci++) { float w = wr[co*129+ci]; GSTEP16(w, g + ci*20); }
    #pragma unroll
    for (int p = 0; p < 16; p++) Y[(r0+p)*CC + co] = acc[p];
  }
}

// ---------------- att1 wmma kernel (256-row tiles) --------------------------
__global__ void __launch_bounds__(256, 1) k_att1_w(const float* __restrict__ xyz,
                                                   const float* __restrict__ p1w,
                                                   const float* __restrict__ p1b) {
  char* smc = (char*)dsm;
  int tid = threadIdx.x, b = blockIdx.y;
  int warp = tid >> 5, lane = tid & 31;
  if (tid < 128) {
    float s1 = g_sc1[b*CC+tid], h1 = g_sh1[b*CC+tid];
    ((float4*)(smc+OFF_CO))[tid] = make_float4(s1*p1w[tid*3], s1*p1w[tid*3+1],
                                               s1*p1w[tid*3+2], fmaf(s1, p1b[tid], h1));
  }
  build_wtile(g_M, smc, tid);
  const float* xb = xyz + (size_t)b*3*NN;
  int er = warp*32 + lane;                      // epilogue/build row (one per thread)
  __nv_bfloat16* Ahp = (__nv_bfloat16*)(smc+OFF_AH) + tid*PA;
  __nv_bfloat16* Alp = (__nv_bfloat16*)(smc+OFF_AL) + tid*PA;
  const float* Drow = (const float*)(smc+OFF_D) + (size_t)er*PD;
  for (int tl = blockIdx.x; tl < 512; tl += gridDim.x) {
    int n0 = tl*16;
    size_t r0 = ((size_t)b*NN + n0)*16;
    __syncthreads();
    {
      int j = g_idx[r0 + tid];
      ((int*)(smc+OFF_JSH))[tid] = j;
      int nq = n0 + (tid >> 4);
      float4 rr;
      rr.x = xb[j]-xb[nq]; rr.y = xb[NN+j]-xb[NN+nq]; rr.z = xb[2*NN+j]-xb[2*NN+nq]; rr.w = 0.f;
      ((float4*)(smc+OFF_REL))[tid] = rr;
    }
    if (tid < 16) ((float*)(smc+OFF_SAC))[tid] = 0.f;
    __syncthreads();
    float4 rl = ((float4*)(smc+OFF_REL))[tid];
    const float4* co4 = (const float4*)(smc+OFF_CO);
    #pragma unroll
    for (int g = 0; g < 16; g++) {
      float v[8];
      #pragma unroll
      for (int i = 0; i < 8; i++) {
        float4 c4 = co4[g*8+i];
        float y = fmaf(c4.x, rl.x, fmaf(c4.y, rl.y, fmaf(c4.z, rl.z, c4.w)));
        v[i] = (y >= 0.f) ? y : 0.1f*y;
      }
      uint4 hi, lo; SPLIT8(v, hi, lo);
      *(uint4*)(Ahp + g*8) = hi;
      *(uint4*)(Alp + g*8) = lo;
    }
    __syncthreads();
    wmma_gemm256(smc, warp);
    __syncthreads();
    int nq = n0 + (er >> 4), j = ((int*)(smc+OFF_JSH))[er];
    const float4* aqp = (const float4*)(g_aq + ((size_t)b*NN + nq)*CC);
    const float4* akp = (const float4*)(g_ak + ((size_t)b*NN + j)*CC);
    const float4* cvp = (const float4*)(g_ccv);
    float4* op = (float4*)(g_t1 + (r0 + er)*CC);
    float ts[8], tss[8];
    #pragma unroll
    for (int g = 0; g < 8; g++) { ts[g] = 0.f; tss[g] = 0.f; }
    #pragma unroll
    for (int q = 0; q < 32; q++) {
      const float4 d = *(const float4*)(Drow + q*4);
      float4 aq = aqp[q], ak = akp[q], cv = cvp[q], vv;
      vv.x = d.x + cv.x + aq.x - ak.x;
      vv.y = d.y + cv.y + aq.y - ak.y;
      vv.z = d.z + cv.z + aq.z - ak.z;
      vv.w = d.w + cv.w + aq.w - ak.w;
      op[q] = vv;
      int g = q >> 2;
      ts[g] += vv.x + vv.y + vv.z + vv.w;
      tss[g] = fmaf(vv.x,vv.x,fmaf(vv.y,vv.y,fmaf(vv.z,vv.z,fmaf(vv.w,vv.w,tss[g]))));
    }
    #pragma unroll
    for (int g = 0; g < 8; g++)
      #pragma unroll
      for (int off = 16; off >= 1; off >>= 1) {
        ts[g]  += __shfl_down_sync(0xffffffffu, ts[g], off);
        tss[g] += __shfl_down_sync(0xffffffffu, tss[g], off);
      }
    if (lane == 0) {
      float* sa = (float*)(smc+OFF_SAC);
      #pragma unroll
      for (int g = 0; g < 8; g++) {
        atomicAdd(&sa[g], ts[g]);
        atomicAdd(&sa[8+g], tss[g]);
      }
    }
    __syncthreads();
    if (tid < 16) g_part2[((size_t)b*512 + tl)*16 + tid] = ((float*)(smc+OFF_SAC))[tid];
  }
}

// ---------------- att2 wmma kernel (softmax + V-agg + residual) -------------
__global__ void __launch_bounds__(256, 1) k_att2_w(const float* __restrict__ W) {
  char* smc = (char*)dsm;
  int tid = threadIdx.x, b = blockIdx.y;
  int warp = tid >> 5, lane = tid & 31;
  if (tid < 128)
    ((float2*)(smc+OFF_CO))[tid] = make_float2(g_sc2[b*CC+tid], g_sh2[b*CC+tid]);
  build_wtile(W, smc, tid);
  int er = warp*32 + lane, kk = er & 15;
  __nv_bfloat16* Ahp = (__nv_bfloat16*)(smc+OFF_AH) + tid*PA;
  __nv_bfloat16* Alp = (__nv_bfloat16*)(smc+OFF_AL) + tid*PA;
  const float* Drow = (const float*)(smc+OFF_D) + (size_t)er*PD;
  for (int tl = blockIdx.x; tl < 512; tl += gridDim.x) {
    int n0 = tl*16;
    size_t r0 = ((size_t)b*NN + n0)*16;
    __syncthreads();
    ((int*)(smc+OFF_JSH))[tid] = g_idx[r0 + tid];
    {
      const float4* tp = (const float4*)(g_t1 + (r0 + tid)*CC);
      const float2* c2 = (const float2*)(smc+OFF_CO);
      #pragma unroll
      for (int g = 0; g < 16; g++) {
        float4 f0 = tp[g*2], f1 = tp[g*2+1];
        float v[8] = {f0.x,f0.y,f0.z,f0.w,f1.x,f1.y,f1.z,f1.w};
        #pragma unroll
        for (int i = 0; i < 8; i++) {
          float2 c = c2[g*8+i];
          float y = fmaf(c.x, v[i], c.y);
          v[i] = (y >= 0.f) ? y : 0.1f*y;
        }
        uint4 hi, lo; SPLIT8(v, hi, lo);
        *(uint4*)(Ahp + g*8) = hi;
        *(uint4*)(Alp + g*8) = lo;
      }
    }
    __syncthreads();
    wmma_gemm256(smc, warp);
    __syncthreads();
    int nq = n0 + (er >> 4), j = ((int*)(smc+OFF_JSH))[er];
    const float4* vp = (const float4*)(g_v + ((size_t)b*NN + j)*CC);
    const float4* np = (const float4*)(g_nf + ((size_t)b*NN + nq)*CC);
    float4* yp = (float4*)(g_y5 + ((size_t)b*NN + nq)*CC);
    #pragma unroll
    for (int q = 0; q < 32; q++) {
      float4 x = *(const float4*)(Drow + q*4);
      float4 m = x;
      #pragma unroll
      for (int off = 8; off >= 1; off >>= 1) {
        m.x = fmaxf(m.x, __shfl_xor_sync(0xffffffffu, m.x, off, 16));
        m.y = fmaxf(m.y, __shfl_xor_sync(0xffffffffu, m.y, off, 16));
        m.z = fmaxf(m.z, __shfl_xor_sync(0xffffffffu, m.z, off, 16));
        m.w = fmaxf(m.w, __shfl_xor_sync(0xffffffffu, m.w, off, 16));
      }
      float4 e;
      e.x = __expf(x.x - m.x); e.y = __expf(x.y - m.y);
      e.z = __expf(x.z - m.z); e.w = __expf(x.w - m.w);
      float4 s = e;
      #pragma unroll
      for (int off = 8; off >= 1; off >>= 1) {
        s.x += __shfl_xor_sync(0xffffffffu, s.x, off, 16);
        s.y += __shfl_xor_sync(0xffffffffu, s.y, off, 16);
        s.z += __shfl_xor_sync(0xffffffffu, s.z, off, 16);
        s.w += __shfl_xor_sync(0xffffffffu, s.w, off, 16);
      }
      float4 vv = vp[q], oo;
      oo.x = e.x/s.x*vv.x; oo.y = e.y/s.y*vv.y;
      oo.z = e.z/s.z*vv.z; oo.w = e.w/s.w*vv.w;
      #pragma unroll
      for (int off = 8; off >= 1; off >>= 1) {
        oo.x += __shfl_xor_sync(0xffffffffu, oo.x, off, 16);
        oo.y += __shfl_xor_sync(0xffffffffu, oo.y, off, 16);
        oo.z += __shfl_xor_sync(0xffffffffu, oo.z, off, 16);
        oo.w += __shfl_xor_sync(0xffffffffu, oo.w, off, 16);
      }
      if (kk == 0) {
        float4 nf = np[q], r;
        r.x = oo.x + nf.x; r.y = oo.y + nf.y; r.z = oo.z + nf.z; r.w = oo.w + nf.w;
        yp[q] = r;
      }
    }
  }
}

// ---------------- post conv + stats -----------------------------------------
__global__ void __launch_bounds__(256) k_conv_post(const float* __restrict__ X,
                                                   const float* __restrict__ W,
                                                   const float* __restrict__ bias,
                                                   float* __restrict__ Y) {
  float* wr = dsm;
  float* gb = dsm + CC*129;
  float* sacc = gb + 2*CC*20;
  int tid = threadIdx.x, grp = tid >> 7, co = tid & 127, lane = tid & 31;
  int b = blockIdx.y;
  for (int e = tid; e < CC*CC; e += 256) wr[(e>>7)*129 + (e&127)] = W[e];
  if (tid < 16) sacc[tid] = 0.f;
  float bv = bias[co];
  float* g = gb + grp*(CC*20);
  float ts = 0.f, tss = 0.f;
  for (int it = 0; it < 2; it++) {
    size_t r0 = (size_t)b*NN + (size_t)(blockIdx.x*2 + it)*32 + grp*16;
    __syncthreads();
    #pragma unroll
    for (int p = 0; p < 16; p++) g[co*20+p] = X[(r0+p)*CC + co];
    __syncthreads();
    float acc[16];
    #pragma unroll
    for (int p = 0; p < 16; p++) acc[p] = bv;
    #pragma unroll 4
    for (int ci = 0; ci < CC; ci++) { float w = wr[co*129+ci]; GSTEP16(w, g + ci*20); }
    #pragma unroll
    for (int p = 0; p < 16; p++) { Y[(r0+p)*CC + co] = acc[p]; ts += acc[p]; tss = fmaf(acc[p],acc[p],tss); }
  }
  #pragma unroll
  for (int off = 8; off >= 1; off >>= 1) {
    ts  += __shfl_down_sync(0xffffffffu, ts, off, 16);
    tss += __shfl_down_sync(0xffffffffu, tss, off, 16);
  }
  if ((lane & 15) == 0) {
    int cgg = co >> 4;
    atomicAdd(&sacc[cgg], ts); atomicAdd(&sacc[8+cgg], tss);
  }
  __syncthreads();
  if (tid < 16) g_part3[((size_t)b*gridDim.x + blockIdx.x)*16 + tid] = sacc[tid];
}

// ---------------- final GN3 + lrelu + transpose -----------------------------
__global__ void k_final(float* __restrict__ out) {
  __shared__ float t[32][33];
  int b = blockIdx.z, c0 = blockIdx.y*32, n0 = blockIdx.x*32;
  int tx = threadIdx.x, ty = threadIdx.y;
  float scv = g_sc3[b*CC + c0 + tx], shv = g_sh3[b*CC + c0 + tx];
  #pragma unroll
  for (int i = 0; i < 4; i++) {
    int n = n0 + ty*4 + i;
    float x = g_aq[((size_t)b*NN + n)*CC + c0 + tx];
    float y = fmaf(scv, x, shv);
    t[tx][ty*4+i] = (y >= 0.f) ? y : 0.1f*y;
  }
  __syncthreads();
  #pragma unroll
  for (int i = 0; i < 4; i++) {
    int c = c0 + ty*4 + i;
    out[((size_t)b*CC + c)*NN + n0 + tx] = t[ty*4+i][tx];
  }
}

// ---------------- launch ----------------------------------------------------
extern "C" void kernel_launch(void* const* d_in, const int* in_sizes, int n_in,
                              void* d_out, int out_size) {
  const float* xyz    = (const float*)d_in[0];
  const float* feat   = (const float*)d_in[1];
  const float* pre_w  = (const float*)d_in[2];
  const float* pre_b  = (const float*)d_in[3];
  const float* wq_w   = (const float*)d_in[4];
  const float* wq_b   = (const float*)d_in[5];
  const float* wk_w   = (const float*)d_in[6];
  const float* wk_b   = (const float*)d_in[7];
  const float* wv_w   = (const float*)d_in[8];
  const float* wv_b   = (const float*)d_in[9];
  const float* pos1_w = (const float*)d_in[10];
  const float* pos1_b = (const float*)d_in[11];
  const float* pos1_g = (const float*)d_in[12];
  const float* pos1_be= (const float*)d_in[13];
  const float* att1_b = (const float*)d_in[17];
  const float* att1_g = (const float*)d_in[18];
  const float* att1_be= (const float*)d_in[19];
  const float* att2_w = (const float*)d_in[20];
  const float* post_w = (const float*)d_in[22];
  const float* post_b = (const float*)d_in[23];
  const float* post_g = (const float*)d_in[24];
  const float* post_be= (const float*)d_in[25];
  float* out = (float*)d_out;

  const int SMEMC = (CC*129 + 2*CC*20 + 16) * 4;
  cudaFuncSetAttribute(k_convQKV,  cudaFuncAttributeMaxDynamicSharedMemorySize, SMEMC);
  cudaFuncSetAttribute(k_conv_post,cudaFuncAttributeMaxDynamicSharedMemorySize, SMEMC);
  cudaFuncSetAttribute(k_att1_w,   cudaFuncAttributeMaxDynamicSharedMemorySize, SMT3);
  cudaFuncSetAttribute(k_att2_w,   cudaFuncAttributeMaxDynamicSharedMemorySize, SMT3);

  void *p_y5, *p_aq;
  cudaGetSymbolAddress(&p_y5, g_y5);
  cudaGetSymbolAddress(&p_aq, g_aq);

  k_knn<<<dim3(NN/128, BB), 128>>>(xyz);                               // 1
  k_prep<<<dim3(256, BB, 2), 256>>>(feat, pre_w, pre_b,                // 2
      (const float*)d_in[16], wq_w, wk_w, (const float*)d_in[14],
      att1_b, wq_b, wk_b, (const float*)d_in[15],
      pos1_w, pos1_b, pos1_g, pos1_be);
  k_convQKV<<<dim3(128, BB, 3), 256, SMEMC>>>(wv_w, att1_b, wv_b);     // 3
  k_att1_w<<<dim3(148, BB), 256, SMT3>>>(xyz, pos1_w, pos1_b);         // 4 = PROFILED
  k_reduce<<<2, 256>>>(1, 512, 1.f/2097152.f, att1_g, att1_be);        // 5
  k_att2_w<<<dim3(148, BB), 256, SMT3>>>(att2_w);                      // 6
  k_conv_post<<<dim3(128, BB), 256, SMEMC>>>((const float*)p_y5, post_w, post_b, (float*)p_aq); // 7
  k_reduce<<<2, 256>>>(2, 128, 1.f/131072.f, post_g, post_be);         // 8
  k_final<<<dim3(NN/32, CC/32, BB), dim3(32, 8)>>>(out);               // 9
}